// round 1
// baseline (speedup 1.0000x reference)
#include <cuda_runtime.h>
#include <math.h>

// Problem constants
#define S_TXT 512
#define S_IMG 2304
#define S_ALL 2816
#define DMODEL 3072
#define NH 24
#define HD 128

// Scratch (static device globals: allocation-free rule)
__device__ float g_Q[S_ALL * DMODEL];
__device__ float g_K[S_ALL * DMODEL];
__device__ float g_V[S_ALL * DMODEL];
__device__ float g_O[S_ALL * DMODEL];

// ---------------------------------------------------------------------------
// 128x128x8 fp32 register-blocked GEMM tile: C[128][128] = A[128][K] * B[128][K]^T + bias
// A, B both row-major with K contiguous (NT gemm). 256 threads, 8x8 per thread.
// Caller pre-offsets A to its tile's row 0, B to its tile's first N-row,
// bias to n0, C to (m0, n0).
// ---------------------------------------------------------------------------
__device__ __forceinline__ void sgemm128_tile(
    const float* __restrict__ A, const float* __restrict__ B,
    const float* __restrict__ bias, float* __restrict__ C,
    int ldc, int K)
{
    __shared__ float As[8][128];
    __shared__ float Bs[8][128];

    const int tid  = threadIdx.x;
    const int tx   = tid & 15;       // 0..15 -> n groups of 8
    const int ty   = tid >> 4;       // 0..15 -> m groups of 8
    const int lrow = tid >> 1;       // 0..127 (load row)
    const int lk4  = (tid & 1) * 4;  // 0 or 4 (load k offset)

    float acc[8][8];
#pragma unroll
    for (int i = 0; i < 8; i++)
#pragma unroll
        for (int j = 0; j < 8; j++) acc[i][j] = 0.0f;

    const float* Aptr = A + (size_t)lrow * K + lk4;
    const float* Bptr = B + (size_t)lrow * K + lk4;

    float4 pa = *(const float4*)Aptr;
    float4 pb = *(const float4*)Bptr;

    for (int k0 = 0; k0 < K; k0 += 8) {
        // store current prefetched tiles (transposed: [k][row])
        As[lk4 + 0][lrow] = pa.x; As[lk4 + 1][lrow] = pa.y;
        As[lk4 + 2][lrow] = pa.z; As[lk4 + 3][lrow] = pa.w;
        Bs[lk4 + 0][lrow] = pb.x; Bs[lk4 + 1][lrow] = pb.y;
        Bs[lk4 + 2][lrow] = pb.z; Bs[lk4 + 3][lrow] = pb.w;
        __syncthreads();

        if (k0 + 8 < K) {
            pa = *(const float4*)(Aptr + k0 + 8);
            pb = *(const float4*)(Bptr + k0 + 8);
        }

#pragma unroll
        for (int k = 0; k < 8; k++) {
            float4 a0 = *(const float4*)&As[k][ty * 8];
            float4 a1 = *(const float4*)&As[k][ty * 8 + 4];
            float4 b0 = *(const float4*)&Bs[k][tx * 8];
            float4 b1 = *(const float4*)&Bs[k][tx * 8 + 4];
            float av[8] = {a0.x, a0.y, a0.z, a0.w, a1.x, a1.y, a1.z, a1.w};
            float bv[8] = {b0.x, b0.y, b0.z, b0.w, b1.x, b1.y, b1.z, b1.w};
#pragma unroll
            for (int i = 0; i < 8; i++)
#pragma unroll
                for (int j = 0; j < 8; j++)
                    acc[i][j] = fmaf(av[i], bv[j], acc[i][j]);
        }
        __syncthreads();
    }

    float bv[8];
#pragma unroll
    for (int j = 0; j < 8; j++) bv[j] = bias[tx * 8 + j];

#pragma unroll
    for (int i = 0; i < 8; i++) {
        int r = ty * 8 + i;
        float4 o0 = make_float4(acc[i][0] + bv[0], acc[i][1] + bv[1],
                                acc[i][2] + bv[2], acc[i][3] + bv[3]);
        float4 o1 = make_float4(acc[i][4] + bv[4], acc[i][5] + bv[5],
                                acc[i][6] + bv[6], acc[i][7] + bv[7]);
        *(float4*)&C[(size_t)r * ldc + tx * 8]     = o0;
        *(float4*)&C[(size_t)r * ldc + tx * 8 + 4] = o1;
    }
}

// ---------------------------------------------------------------------------
// Kernel 1: fused QKV projection for txt+img (txt rows first: concat order)
// grid: (D/128, S_ALL/128, 3) -> z: 0=Q 1=K 2=V
// ---------------------------------------------------------------------------
__global__ __launch_bounds__(256) void qkv_kernel(
    const float* __restrict__ hid, const float* __restrict__ enc,
    const float* __restrict__ wq,  const float* __restrict__ bq,
    const float* __restrict__ wk,  const float* __restrict__ bk,
    const float* __restrict__ wv,  const float* __restrict__ bv,
    const float* __restrict__ waq, const float* __restrict__ baq,
    const float* __restrict__ wak, const float* __restrict__ bak,
    const float* __restrict__ wav, const float* __restrict__ bav)
{
    const int n0 = blockIdx.x * 128;
    const int m0 = blockIdx.y * 128;
    const int z  = blockIdx.z;

    const float* A;
    const float* W;
    const float* bias;
    if (m0 < S_TXT) {
        A    = enc + (size_t)m0 * DMODEL;
        W    = (z == 0) ? waq : (z == 1) ? wak : wav;
        bias = (z == 0) ? baq : (z == 1) ? bak : bav;
    } else {
        A    = hid + (size_t)(m0 - S_TXT) * DMODEL;
        W    = (z == 0) ? wq : (z == 1) ? wk : wv;
        bias = (z == 0) ? bq : (z == 1) ? bk : bv;
    }
    float* Cbase = (z == 0) ? g_Q : (z == 1) ? g_K : g_V;
    float* C = Cbase + (size_t)m0 * DMODEL + n0;

    sgemm128_tile(A, W + (size_t)n0 * DMODEL, bias + n0, C, DMODEL, DMODEL);
}

// ---------------------------------------------------------------------------
// Kernel 2: per-head RMSNorm + RoPE on Q and K (in place)
// grid: (S_ALL*NH, 2), block: 128 threads (one head vector)
// ---------------------------------------------------------------------------
__global__ __launch_bounds__(128) void rmsrope_kernel(
    const float* __restrict__ nq,  const float* __restrict__ nk,
    const float* __restrict__ naq, const float* __restrict__ nak,
    const float* __restrict__ img_cos, const float* __restrict__ img_sin,
    const float* __restrict__ txt_cos, const float* __restrict__ txt_sin)
{
    const int sh = blockIdx.x;
    const int s  = sh / NH;
    const int h  = sh - s * NH;
    const int which = blockIdx.y;  // 0 = Q, 1 = K

    float* buf = which ? g_K : g_Q;
    const float *nw, *ctab, *stab;
    int srow;
    if (s < S_TXT) {
        nw = which ? nak : naq; ctab = txt_cos; stab = txt_sin; srow = s;
    } else {
        nw = which ? nk : nq;   ctab = img_cos; stab = img_sin; srow = s - S_TXT;
    }

    const int d = threadIdx.x;  // 0..127
    float* p = buf + (size_t)s * DMODEL + h * HD;
    float v = p[d];

    // sum of squares over the 128-dim head
    float ss = v * v;
#pragma unroll
    for (int o = 16; o > 0; o >>= 1) ss += __shfl_xor_sync(0xffffffffu, ss, o);
    __shared__ float wsum[4];
    if ((d & 31) == 0) wsum[d >> 5] = ss;
    __syncthreads();
    ss = wsum[0] + wsum[1] + wsum[2] + wsum[3];

    float inv = rsqrtf(ss * (1.0f / HD) + 1e-6f);
    v = v * inv * nw[d];

    // rope: pair (x[2i], x[2i+1])
    float partner = __shfl_xor_sync(0xffffffffu, v, 1);
    float c  = ctab[(size_t)srow * (HD / 2) + (d >> 1)];
    float sn = stab[(size_t)srow * (HD / 2) + (d >> 1)];
    float out = (d & 1) ? fmaf(partner, sn, v * c) : (v * c - partner * sn);
    p[d] = out;
}

// ---------------------------------------------------------------------------
// Kernel 3: flash attention, fp32. grid: (S_ALL/64, NH), 256 threads.
// Q tile 64 x 128, KV tiles 64 x 128, online softmax.
// ---------------------------------------------------------------------------
#define QT 64
#define KT 64
#define PS_LD 65
#define FLASH_SMEM_FLOATS (HD * QT + HD * KT + KT * HD + QT * PS_LD + 3 * QT)
#define FLASH_SMEM_BYTES  (FLASH_SMEM_FLOATS * 4)

extern __shared__ float fa_sm[];

__global__ __launch_bounds__(256) void flash_kernel()
{
    float* Qs   = fa_sm;                  // [HD][QT] transposed
    float* Ks   = Qs + HD * QT;           // [HD][KT] transposed
    float* Vs   = Ks + HD * KT;           // [KT][HD] natural
    float* Ps   = Vs + KT * HD;           // [QT][PS_LD]
    float* m_s  = Ps + QT * PS_LD;
    float* l_s  = m_s + QT;
    float* al_s = l_s + QT;

    const int h  = blockIdx.y;
    const int q0 = blockIdx.x * QT;
    const int tid = threadIdx.x;
    const int tx = tid & 15;   // col group (4 cols)
    const int ty = tid >> 4;   // row group (4 rows)
    const int hoff = h * HD;

    const float scale = 0.08838834764831845f;  // 1/sqrt(128)

    // load Q tile (transposed, pre-scaled)
    for (int idx = tid; idx < QT * (HD / 4); idx += 256) {
        int r  = idx >> 5;          // 0..63
        int c4 = (idx & 31) << 2;   // 0..124
        float4 v = *(const float4*)&g_Q[(size_t)(q0 + r) * DMODEL + hoff + c4];
        Qs[(c4 + 0) * QT + r] = v.x * scale;
        Qs[(c4 + 1) * QT + r] = v.y * scale;
        Qs[(c4 + 2) * QT + r] = v.z * scale;
        Qs[(c4 + 3) * QT + r] = v.w * scale;
    }
    if (tid < QT) { m_s[tid] = -1e30f; l_s[tid] = 0.0f; }

    float acc[4][8];
#pragma unroll
    for (int i = 0; i < 4; i++)
#pragma unroll
        for (int j = 0; j < 8; j++) acc[i][j] = 0.0f;

    __syncthreads();

    for (int kt = 0; kt < S_ALL / KT; kt++) {
        const int k0 = kt * KT;
        // load K (transposed) and V (natural)
        for (int idx = tid; idx < KT * (HD / 4); idx += 256) {
            int r  = idx >> 5;
            int c4 = (idx & 31) << 2;
            float4 kv = *(const float4*)&g_K[(size_t)(k0 + r) * DMODEL + hoff + c4];
            Ks[(c4 + 0) * KT + r] = kv.x;
            Ks[(c4 + 1) * KT + r] = kv.y;
            Ks[(c4 + 2) * KT + r] = kv.z;
            Ks[(c4 + 3) * KT + r] = kv.w;
            float4 vv = *(const float4*)&g_V[(size_t)(k0 + r) * DMODEL + hoff + c4];
            *(float4*)&Vs[r * HD + c4] = vv;
        }
        __syncthreads();

        // GEMM1: S = (Q*scale) K^T, 4x4 per thread
        float s4[4][4];
#pragma unroll
        for (int i = 0; i < 4; i++)
#pragma unroll
            for (int j = 0; j < 4; j++) s4[i][j] = 0.0f;

#pragma unroll 8
        for (int d = 0; d < HD; d++) {
            float4 a = *(const float4*)&Qs[d * QT + (ty << 2)];
            float4 b = *(const float4*)&Ks[d * KT + (tx << 2)];
            float av[4] = {a.x, a.y, a.z, a.w};
            float bvv[4] = {b.x, b.y, b.z, b.w};
#pragma unroll
            for (int i = 0; i < 4; i++)
#pragma unroll
                for (int j = 0; j < 4; j++)
                    s4[i][j] = fmaf(av[i], bvv[j], s4[i][j]);
        }
#pragma unroll
        for (int i = 0; i < 4; i++)
#pragma unroll
            for (int j = 0; j < 4; j++)
                Ps[(ty * 4 + i) * PS_LD + tx * 4 + j] = s4[i][j];
        __syncthreads();

        // online softmax: one thread per row
        if (tid < QT) {
            const int r = tid;
            float mo = m_s[r];
            float mx = mo;
#pragma unroll 8
            for (int k = 0; k < KT; k++) mx = fmaxf(mx, Ps[r * PS_LD + k]);
            float al = __expf(mo - mx);
            float rs = 0.0f;
#pragma unroll 8
            for (int k = 0; k < KT; k++) {
                float pv = __expf(Ps[r * PS_LD + k] - mx);
                Ps[r * PS_LD + k] = pv;
                rs += pv;
            }
            m_s[r]  = mx;
            l_s[r]  = l_s[r] * al + rs;
            al_s[r] = al;
        }
        __syncthreads();

        // rescale existing accumulators
        float alv[4];
#pragma unroll
        for (int i = 0; i < 4; i++) alv[i] = al_s[ty * 4 + i];
#pragma unroll
        for (int i = 0; i < 4; i++)
#pragma unroll
            for (int j = 0; j < 8; j++) acc[i][j] *= alv[i];

        // GEMM2: O += P V
#pragma unroll 4
        for (int k = 0; k < KT; k++) {
            float pv[4];
#pragma unroll
            for (int i = 0; i < 4; i++) pv[i] = Ps[(ty * 4 + i) * PS_LD + k];
            float4 v0 = *(const float4*)&Vs[k * HD + (tx << 2)];
            float4 v1 = *(const float4*)&Vs[k * HD + 64 + (tx << 2)];
            float vv[8] = {v0.x, v0.y, v0.z, v0.w, v1.x, v1.y, v1.z, v1.w};
#pragma unroll
            for (int i = 0; i < 4; i++)
#pragma unroll
                for (int j = 0; j < 8; j++)
                    acc[i][j] = fmaf(pv[i], vv[j], acc[i][j]);
        }
        __syncthreads();
    }

    // epilogue: divide by l, write out
#pragma unroll
    for (int i = 0; i < 4; i++) {
        int r = ty * 4 + i;
        float invl = 1.0f / l_s[r];
        float4 o0 = make_float4(acc[i][0] * invl, acc[i][1] * invl,
                                acc[i][2] * invl, acc[i][3] * invl);
        float4 o1 = make_float4(acc[i][4] * invl, acc[i][5] * invl,
                                acc[i][6] * invl, acc[i][7] * invl);
        *(float4*)&g_O[(size_t)(q0 + r) * DMODEL + hoff + (tx << 2)]      = o0;
        *(float4*)&g_O[(size_t)(q0 + r) * DMODEL + hoff + 64 + (tx << 2)] = o1;
    }
}

// ---------------------------------------------------------------------------
// Kernel 4: output projections. grid: (D/128, S_ALL/128)
// rows [0,512): txt -> w_add_out -> d_out + S_IMG*D
// rows [512,2816): img -> w_out -> d_out
// ---------------------------------------------------------------------------
__global__ __launch_bounds__(256) void outproj_kernel(
    const float* __restrict__ w_out,     const float* __restrict__ b_out,
    const float* __restrict__ w_add_out, const float* __restrict__ b_add_out,
    float* __restrict__ out)
{
    const int n0 = blockIdx.x * 128;
    const int m0 = blockIdx.y * 128;
    const float* A = g_O + (size_t)m0 * DMODEL;
    const float* W;
    const float* bias;
    float* C;
    if (m0 < S_TXT) {
        W = w_add_out; bias = b_add_out;
        C = out + (size_t)S_IMG * DMODEL + (size_t)m0 * DMODEL;
    } else {
        W = w_out; bias = b_out;
        C = out + (size_t)(m0 - S_TXT) * DMODEL;
    }
    sgemm128_tile(A, W + (size_t)n0 * DMODEL, bias + n0, C + n0, DMODEL, DMODEL);
}

// ---------------------------------------------------------------------------
extern "C" void kernel_launch(void* const* d_in, const int* in_sizes, int n_in,
                              void* d_out, int out_size)
{
    const float* hid   = (const float*)d_in[0];
    const float* enc   = (const float*)d_in[1];
    const float* wq    = (const float*)d_in[2];
    const float* bq    = (const float*)d_in[3];
    const float* wk    = (const float*)d_in[4];
    const float* bk    = (const float*)d_in[5];
    const float* wv    = (const float*)d_in[6];
    const float* bv    = (const float*)d_in[7];
    const float* waq   = (const float*)d_in[8];
    const float* baq   = (const float*)d_in[9];
    const float* wak   = (const float*)d_in[10];
    const float* bak   = (const float*)d_in[11];
    const float* wav   = (const float*)d_in[12];
    const float* bav   = (const float*)d_in[13];
    const float* nq    = (const float*)d_in[14];
    const float* nk    = (const float*)d_in[15];
    const float* naq   = (const float*)d_in[16];
    const float* nak   = (const float*)d_in[17];
    const float* w_out     = (const float*)d_in[18];
    const float* b_out     = (const float*)d_in[19];
    const float* w_add_out = (const float*)d_in[20];
    const float* b_add_out = (const float*)d_in[21];
    const float* img_cos = (const float*)d_in[22];
    const float* img_sin = (const float*)d_in[23];
    const float* txt_cos = (const float*)d_in[24];
    const float* txt_sin = (const float*)d_in[25];

    float* out = (float*)d_out;

    dim3 gq(DMODEL / 128, S_ALL / 128, 3);
    qkv_kernel<<<gq, 256>>>(hid, enc, wq, bq, wk, bk, wv, bv,
                            waq, baq, wak, bak, wav, bav);

    rmsrope_kernel<<<dim3(S_ALL * NH, 2), 128>>>(nq, nk, naq, nak,
                                                 img_cos, img_sin,
                                                 txt_cos, txt_sin);

    cudaFuncSetAttribute(flash_kernel,
                         cudaFuncAttributeMaxDynamicSharedMemorySize,
                         FLASH_SMEM_BYTES);
    flash_kernel<<<dim3(S_ALL / QT, NH), 256, FLASH_SMEM_BYTES>>>();

    outproj_kernel<<<dim3(DMODEL / 128, S_ALL / 128), 256>>>(
        w_out, b_out, w_add_out, b_add_out, out);
}

// round 3
// speedup vs baseline: 1.3814x; 1.3814x over previous
#include <cuda_runtime.h>
#include <cuda_bf16.h>
#include <cstdint>
#include <math.h>

// Problem constants
#define S_TXT 512
#define S_IMG 2304
#define S_ALL 2816
#define DMODEL 3072
#define NH 24
#define HD 128

// ---------------------------------------------------------------------------
// Static device scratch (allocation-free rule)
// ---------------------------------------------------------------------------
__device__ float g_Q[S_ALL * DMODEL];
__device__ float g_K[S_ALL * DMODEL];
__device__ float g_V[S_ALL * DMODEL];
__device__ float g_O[S_ALL * DMODEL];

__device__ __nv_bfloat16 g_Xhi[S_ALL * DMODEL];
__device__ __nv_bfloat16 g_Xlo[S_ALL * DMODEL];
__device__ __nv_bfloat16 g_Ohi[S_ALL * DMODEL];
__device__ __nv_bfloat16 g_Olo[S_ALL * DMODEL];
// 8 weight matrices: 0=wq 1=wk 2=wv 3=waq 4=wak 5=wav 6=w_out 7=w_add_out
__device__ __nv_bfloat16 g_Whi[(size_t)8 * DMODEL * DMODEL];
__device__ __nv_bfloat16 g_Wlo[(size_t)8 * DMODEL * DMODEL];

// ---------------------------------------------------------------------------
// helpers
// ---------------------------------------------------------------------------
__device__ __forceinline__ uint32_t smem_u32(const void* p) {
    uint32_t a;
    asm("{ .reg .u64 t; cvta.to.shared.u64 t, %1; cvt.u32.u64 %0, t; }"
        : "=r"(a) : "l"(p));
    return a;
}

__device__ __forceinline__ void cp_async16(uint32_t dst, const void* src) {
    asm volatile("cp.async.cg.shared.global [%0], [%1], 16;"
                 :: "r"(dst), "l"(src));
}
__device__ __forceinline__ void cp_commit() {
    asm volatile("cp.async.commit_group;");
}
template <int N>
__device__ __forceinline__ void cp_wait() {
    asm volatile("cp.async.wait_group %0;" :: "n"(N));
}

__device__ __forceinline__ void ldsm_x4(uint32_t* r, uint32_t addr) {
    asm volatile("ldmatrix.sync.aligned.m8n8.x4.shared.b16 {%0,%1,%2,%3}, [%4];"
                 : "=r"(r[0]), "=r"(r[1]), "=r"(r[2]), "=r"(r[3]) : "r"(addr));
}

__device__ __forceinline__ void mma16816(float* d, const uint32_t* a,
                                         const uint32_t* b) {
    asm volatile(
        "mma.sync.aligned.m16n8k16.row.col.f32.bf16.bf16.f32 "
        "{%0,%1,%2,%3}, {%4,%5,%6,%7}, {%8,%9}, {%0,%1,%2,%3};"
        : "+f"(d[0]), "+f"(d[1]), "+f"(d[2]), "+f"(d[3])
        : "r"(a[0]), "r"(a[1]), "r"(a[2]), "r"(a[3]), "r"(b[0]), "r"(b[1]));
}

// ---------------------------------------------------------------------------
// fp32 -> (bf16 hi, bf16 lo) split prepass
// ---------------------------------------------------------------------------
__device__ __forceinline__ void split_store4(
    float4 v, __nv_bfloat16* hi, __nv_bfloat16* lo)
{
    __nv_bfloat16 h0 = __float2bfloat16(v.x);
    __nv_bfloat16 h1 = __float2bfloat16(v.y);
    __nv_bfloat16 h2 = __float2bfloat16(v.z);
    __nv_bfloat16 h3 = __float2bfloat16(v.w);
    __nv_bfloat16 l0 = __float2bfloat16(v.x - __bfloat162float(h0));
    __nv_bfloat16 l1 = __float2bfloat16(v.y - __bfloat162float(h1));
    __nv_bfloat16 l2 = __float2bfloat16(v.z - __bfloat162float(h2));
    __nv_bfloat16 l3 = __float2bfloat16(v.w - __bfloat162float(h3));
    __nv_bfloat162 H0 = {h0, h1}, H1 = {h2, h3};
    __nv_bfloat162 L0 = {l0, l1}, L1 = {l2, l3};
    uint2 Hv, Lv;
    Hv.x = *(uint32_t*)&H0; Hv.y = *(uint32_t*)&H1;
    Lv.x = *(uint32_t*)&L0; Lv.y = *(uint32_t*)&L1;
    *(uint2*)hi = Hv;
    *(uint2*)lo = Lv;
}

__global__ __launch_bounds__(256) void split_x_kernel(
    const float* __restrict__ hid, const float* __restrict__ enc)
{
    size_t i = (size_t)blockIdx.x * blockDim.x + threadIdx.x;
    size_t n4 = (size_t)S_ALL * DMODEL / 4;
    if (i >= n4) return;
    size_t e = i * 4;
    size_t row = e / DMODEL;
    const float* src = (row < S_TXT) ? (enc + e)
                                     : (hid + (e - (size_t)S_TXT * DMODEL));
    split_store4(*(const float4*)src, g_Xhi + e, g_Xlo + e);
}

__global__ __launch_bounds__(256) void split_o_kernel()
{
    size_t i = (size_t)blockIdx.x * blockDim.x + threadIdx.x;
    size_t n4 = (size_t)S_ALL * DMODEL / 4;
    if (i >= n4) return;
    size_t e = i * 4;
    split_store4(*(const float4*)(g_O + e), g_Ohi + e, g_Olo + e);
}

__global__ __launch_bounds__(256) void split_w_kernel(
    const float* __restrict__ w0, const float* __restrict__ w1,
    const float* __restrict__ w2, const float* __restrict__ w3,
    const float* __restrict__ w4, const float* __restrict__ w5,
    const float* __restrict__ w6, const float* __restrict__ w7)
{
    const float* ws[8] = {w0, w1, w2, w3, w4, w5, w6, w7};
    int widx = blockIdx.y;
    size_t i = (size_t)blockIdx.x * blockDim.x + threadIdx.x;
    size_t n4 = (size_t)DMODEL * DMODEL / 4;
    if (i >= n4) return;
    size_t e = i * 4;
    size_t base = (size_t)widx * DMODEL * DMODEL;
    split_store4(*(const float4*)(ws[widx] + e), g_Whi + base + e, g_Wlo + base + e);
}

// ---------------------------------------------------------------------------
// mma.sync split-bf16 GEMM: C[128x128] = A[128,K] B[128,K]^T + bias
// 3 passes: AhBh + AhBl + AlBh. 256 threads (8 warps, each 32x64).
// ---------------------------------------------------------------------------
#define BM 128
#define BN 128
#define BK 32
#define LDS 40                               // halves per SMEM row (32 + 8 pad)
#define ARR_HALVES (128 * LDS)               // 5120 halves per sub-tile
#define STAGE_HALVES (4 * ARR_HALVES)        // Ah | Al | Bh | Bl
#define GEMM_SMEM_BYTES (2 * STAGE_HALVES * 2)   // 81920

extern __shared__ char dyn_sm[];

__device__ __forceinline__ void gemm_load_stage(
    uint32_t stage, const __nv_bfloat16* __restrict__ Ahi,
    const __nv_bfloat16* __restrict__ Alo,
    const __nv_bfloat16* __restrict__ Bhi,
    const __nv_bfloat16* __restrict__ Blo, int k0, int tid)
{
#pragma unroll
    for (int t = 0; t < 8; t++) {
        int i   = tid + t * 256;       // 0..2047
        int arr = i >> 9;              // 0..3
        int idx = i & 511;
        int row = idx >> 2;            // 0..127
        int c   = (idx & 3) * 8;       // halves offset 0,8,16,24
        const __nv_bfloat16* g = (arr == 0) ? Ahi : (arr == 1) ? Alo
                               : (arr == 2) ? Bhi : Blo;
        uint32_t dst = stage + (uint32_t)(arr * ARR_HALVES + row * LDS + c) * 2;
        cp_async16(dst, g + (size_t)row * DMODEL + k0 + c);
    }
}

__device__ __forceinline__ void gemm_tile_mma(
    const __nv_bfloat16* __restrict__ Ahi, const __nv_bfloat16* __restrict__ Alo,
    const __nv_bfloat16* __restrict__ Bhi, const __nv_bfloat16* __restrict__ Blo,
    const float* __restrict__ bias, float* __restrict__ C, int ldc)
{
    const uint32_t smem_base = smem_u32(dyn_sm);
    const int tid  = threadIdx.x;
    const int wid  = tid >> 5;
    const int lane = tid & 31;
    const int wm   = wid & 3;     // m offset 32*wm
    const int wn   = wid >> 2;    // n offset 64*wn

    float d[2][8][4];
#pragma unroll
    for (int mt = 0; mt < 2; mt++)
#pragma unroll
        for (int nt = 0; nt < 8; nt++)
#pragma unroll
            for (int j = 0; j < 4; j++) d[mt][nt][j] = 0.0f;

    const int NCH = DMODEL / BK;  // 96

    gemm_load_stage(smem_base, Ahi, Alo, Bhi, Blo, 0, tid);
    cp_commit();

    const int lrow = lane & 15;
    const int lcol = (lane >> 4) * 8;

    for (int kc = 0; kc < NCH; kc++) {
        const uint32_t stage = smem_base + (uint32_t)(kc & 1) * (STAGE_HALVES * 2);
        if (kc + 1 < NCH) {
            gemm_load_stage(smem_base + (uint32_t)((kc + 1) & 1) * (STAGE_HALVES * 2),
                            Ahi, Alo, Bhi, Blo, (kc + 1) * BK, tid);
            cp_commit();
            cp_wait<1>();
        } else {
            cp_wait<0>();
        }
        __syncthreads();

#pragma unroll
        for (int ks = 0; ks < 2; ks++) {
            // A fragments (hi, lo) for 2 m-tiles
            uint32_t a_h[2][4], a_l[2][4];
#pragma unroll
            for (int mt = 0; mt < 2; mt++) {
                uint32_t addr = stage +
                    (uint32_t)((wm * 32 + mt * 16 + lrow) * LDS + ks * 16 + lcol) * 2;
                ldsm_x4(a_h[mt], addr);
                ldsm_x4(a_l[mt], addr + ARR_HALVES * 2);
            }
            // B fragments (hi, lo) for 8 n-tiles (4 x4-ldmatrix each plane)
            uint32_t b_h[8][2], b_l[8][2];
#pragma unroll
            for (int ng = 0; ng < 4; ng++) {
                uint32_t addr = stage + (uint32_t)(2 * ARR_HALVES) * 2 +
                    (uint32_t)((wn * 64 + ng * 16 + lrow) * LDS + ks * 16 + lcol) * 2;
                uint32_t r[4];
                ldsm_x4(r, addr);
                b_h[2 * ng][0] = r[0]; b_h[2 * ng][1] = r[2];
                b_h[2 * ng + 1][0] = r[1]; b_h[2 * ng + 1][1] = r[3];
                ldsm_x4(r, addr + ARR_HALVES * 2);
                b_l[2 * ng][0] = r[0]; b_l[2 * ng][1] = r[2];
                b_l[2 * ng + 1][0] = r[1]; b_l[2 * ng + 1][1] = r[3];
            }
#pragma unroll
            for (int mt = 0; mt < 2; mt++)
#pragma unroll
                for (int nt = 0; nt < 8; nt++) {
                    mma16816(d[mt][nt], a_h[mt], b_h[nt]);
                    mma16816(d[mt][nt], a_h[mt], b_l[nt]);
                    mma16816(d[mt][nt], a_l[mt], b_h[nt]);
                }
        }
        __syncthreads();
    }

    // epilogue
#pragma unroll
    for (int mt = 0; mt < 2; mt++) {
        int r0 = wm * 32 + mt * 16 + (lane >> 2);
#pragma unroll
        for (int nt = 0; nt < 8; nt++) {
            int c0 = wn * 64 + nt * 8 + (lane & 3) * 2;
            float b0 = bias[c0], b1 = bias[c0 + 1];
            float2 v0 = make_float2(d[mt][nt][0] + b0, d[mt][nt][1] + b1);
            float2 v1 = make_float2(d[mt][nt][2] + b0, d[mt][nt][3] + b1);
            *(float2*)&C[(size_t)r0 * ldc + c0]       = v0;
            *(float2*)&C[(size_t)(r0 + 8) * ldc + c0] = v1;
        }
    }
}

// QKV projection: grid (3072/BN, 2816/BM, 3)
__global__ __launch_bounds__(256, 1) void qkv_gemm_kernel(
    const float* __restrict__ bq,  const float* __restrict__ bk,
    const float* __restrict__ bv,  const float* __restrict__ baq,
    const float* __restrict__ bak, const float* __restrict__ bav)
{
    const int n0 = blockIdx.x * BN;
    const int m0 = blockIdx.y * BM;
    const int z  = blockIdx.z;
    const bool txt = (m0 < S_TXT);
    const int widx = txt ? (3 + z) : z;
    const float* bias = (z == 0) ? (txt ? baq : bq)
                      : (z == 1) ? (txt ? bak : bk)
                                 : (txt ? bav : bv);
    float* C = ((z == 0) ? g_Q : (z == 1) ? g_K : g_V)
               + (size_t)m0 * DMODEL + n0;
    const size_t wb = (size_t)widx * DMODEL * DMODEL + (size_t)n0 * DMODEL;
    gemm_tile_mma(g_Xhi + (size_t)m0 * DMODEL, g_Xlo + (size_t)m0 * DMODEL,
                  g_Whi + wb, g_Wlo + wb, bias + n0, C, DMODEL);
}

// Output projections: grid (3072/BN, 2816/BM)
__global__ __launch_bounds__(256, 1) void outproj_gemm_kernel(
    const float* __restrict__ b_out, const float* __restrict__ b_add_out,
    float* __restrict__ out)
{
    const int n0 = blockIdx.x * BN;
    const int m0 = blockIdx.y * BM;
    const bool txt = (m0 < S_TXT);
    const int widx = txt ? 7 : 6;
    const float* bias = txt ? b_add_out : b_out;
    float* C = txt ? (out + ((size_t)S_IMG + m0) * DMODEL + n0)
                   : (out + (size_t)(m0 - S_TXT) * DMODEL + n0);
    const size_t wb = (size_t)widx * DMODEL * DMODEL + (size_t)n0 * DMODEL;
    gemm_tile_mma(g_Ohi + (size_t)m0 * DMODEL, g_Olo + (size_t)m0 * DMODEL,
                  g_Whi + wb, g_Wlo + wb, bias + n0, C, DMODEL);
}

// ---------------------------------------------------------------------------
// per-head RMSNorm + RoPE on Q and K (in place)
// ---------------------------------------------------------------------------
__global__ __launch_bounds__(128) void rmsrope_kernel(
    const float* __restrict__ nq,  const float* __restrict__ nk,
    const float* __restrict__ naq, const float* __restrict__ nak,
    const float* __restrict__ img_cos, const float* __restrict__ img_sin,
    const float* __restrict__ txt_cos, const float* __restrict__ txt_sin)
{
    const int sh = blockIdx.x;
    const int s  = sh / NH;
    const int h  = sh - s * NH;
    const int which = blockIdx.y;

    float* buf = which ? g_K : g_Q;
    const float *nw, *ctab, *stab;
    int srow;
    if (s < S_TXT) {
        nw = which ? nak : naq; ctab = txt_cos; stab = txt_sin; srow = s;
    } else {
        nw = which ? nk : nq;   ctab = img_cos; stab = img_sin; srow = s - S_TXT;
    }

    const int d = threadIdx.x;
    float* p = buf + (size_t)s * DMODEL + h * HD;
    float v = p[d];

    float ss = v * v;
#pragma unroll
    for (int o = 16; o > 0; o >>= 1) ss += __shfl_xor_sync(0xffffffffu, ss, o);
    __shared__ float wsum[4];
    if ((d & 31) == 0) wsum[d >> 5] = ss;
    __syncthreads();
    ss = wsum[0] + wsum[1] + wsum[2] + wsum[3];

    float inv = rsqrtf(ss * (1.0f / HD) + 1e-6f);
    v = v * inv * nw[d];

    float partner = __shfl_xor_sync(0xffffffffu, v, 1);
    float c  = ctab[(size_t)srow * (HD / 2) + (d >> 1)];
    float sn = stab[(size_t)srow * (HD / 2) + (d >> 1)];
    float outv = (d & 1) ? fmaf(partner, sn, v * c) : (v * c - partner * sn);
    p[d] = outv;
}

// ---------------------------------------------------------------------------
// flash attention fp32 (unchanged, known-good)
// ---------------------------------------------------------------------------
#define QT 64
#define KT 64
#define PS_LD 65
#define FLASH_SMEM_FLOATS (HD * QT + HD * KT + KT * HD + QT * PS_LD + 3 * QT)
#define FLASH_SMEM_BYTES  (FLASH_SMEM_FLOATS * 4)

__global__ __launch_bounds__(256) void flash_kernel()
{
    float* fa_sm = (float*)dyn_sm;
    float* Qs   = fa_sm;
    float* Ks   = Qs + HD * QT;
    float* Vs   = Ks + HD * KT;
    float* Ps   = Vs + KT * HD;
    float* m_s  = Ps + QT * PS_LD;
    float* l_s  = m_s + QT;
    float* al_s = l_s + QT;

    const int h  = blockIdx.y;
    const int q0 = blockIdx.x * QT;
    const int tid = threadIdx.x;
    const int tx = tid & 15;
    const int ty = tid >> 4;
    const int hoff = h * HD;

    const float scale = 0.08838834764831845f;

    for (int idx = tid; idx < QT * (HD / 4); idx += 256) {
        int r  = idx >> 5;
        int c4 = (idx & 31) << 2;
        float4 v = *(const float4*)&g_Q[(size_t)(q0 + r) * DMODEL + hoff + c4];
        Qs[(c4 + 0) * QT + r] = v.x * scale;
        Qs[(c4 + 1) * QT + r] = v.y * scale;
        Qs[(c4 + 2) * QT + r] = v.z * scale;
        Qs[(c4 + 3) * QT + r] = v.w * scale;
    }
    if (tid < QT) { m_s[tid] = -1e30f; l_s[tid] = 0.0f; }

    float acc[4][8];
#pragma unroll
    for (int i = 0; i < 4; i++)
#pragma unroll
        for (int j = 0; j < 8; j++) acc[i][j] = 0.0f;

    __syncthreads();

    for (int kt = 0; kt < S_ALL / KT; kt++) {
        const int k0 = kt * KT;
        for (int idx = tid; idx < KT * (HD / 4); idx += 256) {
            int r  = idx >> 5;
            int c4 = (idx & 31) << 2;
            float4 kv = *(const float4*)&g_K[(size_t)(k0 + r) * DMODEL + hoff + c4];
            Ks[(c4 + 0) * KT + r] = kv.x;
            Ks[(c4 + 1) * KT + r] = kv.y;
            Ks[(c4 + 2) * KT + r] = kv.z;
            Ks[(c4 + 3) * KT + r] = kv.w;
            float4 vv = *(const float4*)&g_V[(size_t)(k0 + r) * DMODEL + hoff + c4];
            *(float4*)&Vs[r * HD + c4] = vv;
        }
        __syncthreads();

        float s4[4][4];
#pragma unroll
        for (int i = 0; i < 4; i++)
#pragma unroll
            for (int j = 0; j < 4; j++) s4[i][j] = 0.0f;

#pragma unroll 8
        for (int d = 0; d < HD; d++) {
            float4 a = *(const float4*)&Qs[d * QT + (ty << 2)];
            float4 b = *(const float4*)&Ks[d * KT + (tx << 2)];
            float av[4] = {a.x, a.y, a.z, a.w};
            float bvv[4] = {b.x, b.y, b.z, b.w};
#pragma unroll
            for (int i = 0; i < 4; i++)
#pragma unroll
                for (int j = 0; j < 4; j++)
                    s4[i][j] = fmaf(av[i], bvv[j], s4[i][j]);
        }
#pragma unroll
        for (int i = 0; i < 4; i++)
#pragma unroll
            for (int j = 0; j < 4; j++)
                Ps[(ty * 4 + i) * PS_LD + tx * 4 + j] = s4[i][j];
        __syncthreads();

        if (tid < QT) {
            const int r = tid;
            float mo = m_s[r];
            float mx = mo;
#pragma unroll 8
            for (int k = 0; k < KT; k++) mx = fmaxf(mx, Ps[r * PS_LD + k]);
            float al = __expf(mo - mx);
            float rs = 0.0f;
#pragma unroll 8
            for (int k = 0; k < KT; k++) {
                float pv = __expf(Ps[r * PS_LD + k] - mx);
                Ps[r * PS_LD + k] = pv;
                rs += pv;
            }
            m_s[r]  = mx;
            l_s[r]  = l_s[r] * al + rs;
            al_s[r] = al;
        }
        __syncthreads();

        float alv[4];
#pragma unroll
        for (int i = 0; i < 4; i++) alv[i] = al_s[ty * 4 + i];
#pragma unroll
        for (int i = 0; i < 4; i++)
#pragma unroll
            for (int j = 0; j < 8; j++) acc[i][j] *= alv[i];

#pragma unroll 4
        for (int k = 0; k < KT; k++) {
            float pv[4];
#pragma unroll
            for (int i = 0; i < 4; i++) pv[i] = Ps[(ty * 4 + i) * PS_LD + k];
            float4 v0 = *(const float4*)&Vs[k * HD + (tx << 2)];
            float4 v1 = *(const float4*)&Vs[k * HD + 64 + (tx << 2)];
            float vv[8] = {v0.x, v0.y, v0.z, v0.w, v1.x, v1.y, v1.z, v1.w};
#pragma unroll
            for (int i = 0; i < 4; i++)
#pragma unroll
                for (int j = 0; j < 8; j++)
                    acc[i][j] = fmaf(pv[i], vv[j], acc[i][j]);
        }
        __syncthreads();
    }

#pragma unroll
    for (int i = 0; i < 4; i++) {
        int r = ty * 4 + i;
        float invl = 1.0f / l_s[r];
        float4 o0 = make_float4(acc[i][0] * invl, acc[i][1] * invl,
                                acc[i][2] * invl, acc[i][3] * invl);
        float4 o1 = make_float4(acc[i][4] * invl, acc[i][5] * invl,
                                acc[i][6] * invl, acc[i][7] * invl);
        *(float4*)&g_O[(size_t)(q0 + r) * DMODEL + hoff + (tx << 2)]      = o0;
        *(float4*)&g_O[(size_t)(q0 + r) * DMODEL + hoff + 64 + (tx << 2)] = o1;
    }
}

// ---------------------------------------------------------------------------
extern "C" void kernel_launch(void* const* d_in, const int* in_sizes, int n_in,
                              void* d_out, int out_size)
{
    const float* hid   = (const float*)d_in[0];
    const float* enc   = (const float*)d_in[1];
    const float* wq    = (const float*)d_in[2];
    const float* bq    = (const float*)d_in[3];
    const float* wk    = (const float*)d_in[4];
    const float* bk    = (const float*)d_in[5];
    const float* wv    = (const float*)d_in[6];
    const float* bv    = (const float*)d_in[7];
    const float* waq   = (const float*)d_in[8];
    const float* baq   = (const float*)d_in[9];
    const float* wak   = (const float*)d_in[10];
    const float* bak   = (const float*)d_in[11];
    const float* wav   = (const float*)d_in[12];
    const float* bav   = (const float*)d_in[13];
    const float* nq    = (const float*)d_in[14];
    const float* nk    = (const float*)d_in[15];
    const float* naq   = (const float*)d_in[16];
    const float* nak   = (const float*)d_in[17];
    const float* w_out     = (const float*)d_in[18];
    const float* b_out     = (const float*)d_in[19];
    const float* w_add_out = (const float*)d_in[20];
    const float* b_add_out = (const float*)d_in[21];
    const float* img_cos = (const float*)d_in[22];
    const float* img_sin = (const float*)d_in[23];
    const float* txt_cos = (const float*)d_in[24];
    const float* txt_sin = (const float*)d_in[25];

    float* out = (float*)d_out;

    // prepass splits
    {
        size_t n4 = (size_t)S_ALL * DMODEL / 4;
        split_x_kernel<<<(unsigned)((n4 + 255) / 256), 256>>>(hid, enc);
        size_t w4 = (size_t)DMODEL * DMODEL / 4;
        dim3 gw((unsigned)((w4 + 255) / 256), 8);
        split_w_kernel<<<gw, 256>>>(wq, wk, wv, waq, wak, wav, w_out, w_add_out);
    }

    // QKV projections on tensor cores (mma.sync, split-bf16 x3)
    cudaFuncSetAttribute(qkv_gemm_kernel,
                         cudaFuncAttributeMaxDynamicSharedMemorySize,
                         GEMM_SMEM_BYTES);
    qkv_gemm_kernel<<<dim3(DMODEL / BN, S_ALL / BM, 3), 256, GEMM_SMEM_BYTES>>>(
        bq, bk, bv, baq, bak, bav);

    rmsrope_kernel<<<dim3(S_ALL * NH, 2), 128>>>(nq, nk, naq, nak,
                                                 img_cos, img_sin,
                                                 txt_cos, txt_sin);

    cudaFuncSetAttribute(flash_kernel,
                         cudaFuncAttributeMaxDynamicSharedMemorySize,
                         FLASH_SMEM_BYTES);
    flash_kernel<<<dim3(S_ALL / QT, NH), 256, FLASH_SMEM_BYTES>>>();

    {
        size_t n4 = (size_t)S_ALL * DMODEL / 4;
        split_o_kernel<<<(unsigned)((n4 + 255) / 256), 256>>>();
    }

    cudaFuncSetAttribute(outproj_gemm_kernel,
                         cudaFuncAttributeMaxDynamicSharedMemorySize,
                         GEMM_SMEM_BYTES);
    outproj_gemm_kernel<<<dim3(DMODEL / BN, S_ALL / BM), 256, GEMM_SMEM_BYTES>>>(
        b_out, b_add_out, out);
}

// round 6
// speedup vs baseline: 2.5512x; 1.8468x over previous
#include <cuda_runtime.h>
#include <cuda_bf16.h>
#include <cstdint>
#include <math.h>

// Problem constants
#define S_TXT 512
#define S_IMG 2304
#define S_ALL 2816
#define DMODEL 3072
#define NH 24
#define HD 128

// ---------------------------------------------------------------------------
// Static device scratch (allocation-free rule)
// ---------------------------------------------------------------------------
__device__ float g_Q[S_ALL * DMODEL];
__device__ float g_K[S_ALL * DMODEL];
__device__ float g_V[S_ALL * DMODEL];

__device__ __nv_bfloat16 g_Xhi[S_ALL * DMODEL];
__device__ __nv_bfloat16 g_Xlo[S_ALL * DMODEL];
__device__ __nv_bfloat16 g_Qh[S_ALL * DMODEL];
__device__ __nv_bfloat16 g_Ql[S_ALL * DMODEL];
__device__ __nv_bfloat16 g_Kh[S_ALL * DMODEL];
__device__ __nv_bfloat16 g_Kl[S_ALL * DMODEL];
__device__ __nv_bfloat16 g_Vh[S_ALL * DMODEL];
__device__ __nv_bfloat16 g_Vl[S_ALL * DMODEL];
__device__ __nv_bfloat16 g_Ohi[S_ALL * DMODEL];
__device__ __nv_bfloat16 g_Olo[S_ALL * DMODEL];
// 8 weight matrices: 0=wq 1=wk 2=wv 3=waq 4=wak 5=wav 6=w_out 7=w_add_out
__device__ __nv_bfloat16 g_Whi[(size_t)8 * DMODEL * DMODEL];
__device__ __nv_bfloat16 g_Wlo[(size_t)8 * DMODEL * DMODEL];

// ---------------------------------------------------------------------------
// helpers
// ---------------------------------------------------------------------------
__device__ __forceinline__ uint32_t smem_u32(const void* p) {
    uint32_t a;
    asm("{ .reg .u64 t; cvta.to.shared.u64 t, %1; cvt.u32.u64 %0, t; }"
        : "=r"(a) : "l"(p));
    return a;
}

__device__ __forceinline__ void cp_async16(uint32_t dst, const void* src) {
    asm volatile("cp.async.cg.shared.global [%0], [%1], 16;"
                 :: "r"(dst), "l"(src));
}
__device__ __forceinline__ void cp_commit() {
    asm volatile("cp.async.commit_group;");
}
template <int N>
__device__ __forceinline__ void cp_wait() {
    asm volatile("cp.async.wait_group %0;" :: "n"(N));
}

__device__ __forceinline__ void ldsm_x4(uint32_t* r, uint32_t addr) {
    asm volatile("ldmatrix.sync.aligned.m8n8.x4.shared.b16 {%0,%1,%2,%3}, [%4];"
                 : "=r"(r[0]), "=r"(r[1]), "=r"(r[2]), "=r"(r[3]) : "r"(addr));
}

__device__ __forceinline__ void ldsm_x4_t(uint32_t* r, uint32_t addr) {
    asm volatile("ldmatrix.sync.aligned.m8n8.x4.trans.shared.b16 {%0,%1,%2,%3}, [%4];"
                 : "=r"(r[0]), "=r"(r[1]), "=r"(r[2]), "=r"(r[3]) : "r"(addr));
}

__device__ __forceinline__ void mma16816(float* d, const uint32_t* a,
                                         const uint32_t* b) {
    asm volatile(
        "mma.sync.aligned.m16n8k16.row.col.f32.bf16.bf16.f32 "
        "{%0,%1,%2,%3}, {%4,%5,%6,%7}, {%8,%9}, {%0,%1,%2,%3};"
        : "+f"(d[0]), "+f"(d[1]), "+f"(d[2]), "+f"(d[3])
        : "r"(a[0]), "r"(a[1]), "r"(a[2]), "r"(a[3]), "r"(b[0]), "r"(b[1]));
}

__device__ __forceinline__ void split_pack2(float f0, float f1,
                                            uint32_t& hi, uint32_t& lo)
{
    __nv_bfloat16 h0 = __float2bfloat16(f0);
    __nv_bfloat16 h1 = __float2bfloat16(f1);
    __nv_bfloat16 l0 = __float2bfloat16(f0 - __bfloat162float(h0));
    __nv_bfloat16 l1 = __float2bfloat16(f1 - __bfloat162float(h1));
    __nv_bfloat162 H = {h0, h1}, L = {l0, l1};
    hi = *(uint32_t*)&H;
    lo = *(uint32_t*)&L;
}

// ---------------------------------------------------------------------------
// fp32 -> (bf16 hi, bf16 lo) split prepass
// ---------------------------------------------------------------------------
__device__ __forceinline__ void split_store4(
    float4 v, __nv_bfloat16* hi, __nv_bfloat16* lo)
{
    uint32_t h0, h1, l0, l1;
    split_pack2(v.x, v.y, h0, l0);
    split_pack2(v.z, v.w, h1, l1);
    uint2 Hv = {h0, h1}, Lv = {l0, l1};
    *(uint2*)hi = Hv;
    *(uint2*)lo = Lv;
}

__global__ __launch_bounds__(256) void split_x_kernel(
    const float* __restrict__ hid, const float* __restrict__ enc)
{
    size_t i = (size_t)blockIdx.x * blockDim.x + threadIdx.x;
    size_t n4 = (size_t)S_ALL * DMODEL / 4;
    if (i >= n4) return;
    size_t e = i * 4;
    size_t row = e / DMODEL;
    const float* src = (row < S_TXT) ? (enc + e)
                                     : (hid + (e - (size_t)S_TXT * DMODEL));
    split_store4(*(const float4*)src, g_Xhi + e, g_Xlo + e);
}

__global__ __launch_bounds__(256) void split_v_kernel()
{
    size_t i = (size_t)blockIdx.x * blockDim.x + threadIdx.x;
    size_t n4 = (size_t)S_ALL * DMODEL / 4;
    if (i >= n4) return;
    size_t e = i * 4;
    split_store4(*(const float4*)(g_V + e), g_Vh + e, g_Vl + e);
}

__global__ __launch_bounds__(256) void split_w_kernel(
    const float* __restrict__ w0, const float* __restrict__ w1,
    const float* __restrict__ w2, const float* __restrict__ w3,
    const float* __restrict__ w4, const float* __restrict__ w5,
    const float* __restrict__ w6, const float* __restrict__ w7)
{
    const float* ws[8] = {w0, w1, w2, w3, w4, w5, w6, w7};
    int widx = blockIdx.y;
    size_t i = (size_t)blockIdx.x * blockDim.x + threadIdx.x;
    size_t n4 = (size_t)DMODEL * DMODEL / 4;
    if (i >= n4) return;
    size_t e = i * 4;
    size_t base = (size_t)widx * DMODEL * DMODEL;
    split_store4(*(const float4*)(ws[widx] + e), g_Whi + base + e, g_Wlo + base + e);
}

// ---------------------------------------------------------------------------
// mma.sync split-bf16 GEMM: C[128x128] = A[128,K] B[128,K]^T + bias
// (verified in R3)
// ---------------------------------------------------------------------------
#define BM 128
#define BN 128
#define BK 32
#define LDS 40
#define ARR_HALVES (128 * LDS)
#define STAGE_HALVES (4 * ARR_HALVES)
#define GEMM_SMEM_BYTES (2 * STAGE_HALVES * 2)

extern __shared__ char dyn_sm[];

__device__ __forceinline__ void gemm_load_stage(
    uint32_t stage, const __nv_bfloat16* __restrict__ Ahi,
    const __nv_bfloat16* __restrict__ Alo,
    const __nv_bfloat16* __restrict__ Bhi,
    const __nv_bfloat16* __restrict__ Blo, int k0, int tid)
{
#pragma unroll
    for (int t = 0; t < 8; t++) {
        int i   = tid + t * 256;
        int arr = i >> 9;
        int idx = i & 511;
        int row = idx >> 2;
        int c   = (idx & 3) * 8;
        const __nv_bfloat16* g = (arr == 0) ? Ahi : (arr == 1) ? Alo
                               : (arr == 2) ? Bhi : Blo;
        uint32_t dst = stage + (uint32_t)(arr * ARR_HALVES + row * LDS + c) * 2;
        cp_async16(dst, g + (size_t)row * DMODEL + k0 + c);
    }
}

__device__ __forceinline__ void gemm_tile_mma(
    const __nv_bfloat16* __restrict__ Ahi, const __nv_bfloat16* __restrict__ Alo,
    const __nv_bfloat16* __restrict__ Bhi, const __nv_bfloat16* __restrict__ Blo,
    const float* __restrict__ bias, float* __restrict__ C, int ldc)
{
    const uint32_t smem_base = smem_u32(dyn_sm);
    const int tid  = threadIdx.x;
    const int wid  = tid >> 5;
    const int lane = tid & 31;
    const int wm   = wid & 3;
    const int wn   = wid >> 2;

    float d[2][8][4];
#pragma unroll
    for (int mt = 0; mt < 2; mt++)
#pragma unroll
        for (int nt = 0; nt < 8; nt++)
#pragma unroll
            for (int j = 0; j < 4; j++) d[mt][nt][j] = 0.0f;

    const int NCH = DMODEL / BK;

    gemm_load_stage(smem_base, Ahi, Alo, Bhi, Blo, 0, tid);
    cp_commit();

    const int lrow = lane & 15;
    const int lcol = (lane >> 4) * 8;

    for (int kc = 0; kc < NCH; kc++) {
        const uint32_t stage = smem_base + (uint32_t)(kc & 1) * (STAGE_HALVES * 2);
        if (kc + 1 < NCH) {
            gemm_load_stage(smem_base + (uint32_t)((kc + 1) & 1) * (STAGE_HALVES * 2),
                            Ahi, Alo, Bhi, Blo, (kc + 1) * BK, tid);
            cp_commit();
            cp_wait<1>();
        } else {
            cp_wait<0>();
        }
        __syncthreads();

#pragma unroll
        for (int ks = 0; ks < 2; ks++) {
            uint32_t a_h[2][4], a_l[2][4];
#pragma unroll
            for (int mt = 0; mt < 2; mt++) {
                uint32_t addr = stage +
                    (uint32_t)((wm * 32 + mt * 16 + lrow) * LDS + ks * 16 + lcol) * 2;
                ldsm_x4(a_h[mt], addr);
                ldsm_x4(a_l[mt], addr + ARR_HALVES * 2);
            }
            uint32_t b_h[8][2], b_l[8][2];
#pragma unroll
            for (int ng = 0; ng < 4; ng++) {
                uint32_t addr = stage + (uint32_t)(2 * ARR_HALVES) * 2 +
                    (uint32_t)((wn * 64 + ng * 16 + lrow) * LDS + ks * 16 + lcol) * 2;
                uint32_t r[4];
                ldsm_x4(r, addr);
                b_h[2 * ng][0] = r[0]; b_h[2 * ng][1] = r[2];
                b_h[2 * ng + 1][0] = r[1]; b_h[2 * ng + 1][1] = r[3];
                ldsm_x4(r, addr + ARR_HALVES * 2);
                b_l[2 * ng][0] = r[0]; b_l[2 * ng][1] = r[2];
                b_l[2 * ng + 1][0] = r[1]; b_l[2 * ng + 1][1] = r[3];
            }
#pragma unroll
            for (int mt = 0; mt < 2; mt++)
#pragma unroll
                for (int nt = 0; nt < 8; nt++) {
                    mma16816(d[mt][nt], a_h[mt], b_h[nt]);
                    mma16816(d[mt][nt], a_h[mt], b_l[nt]);
                    mma16816(d[mt][nt], a_l[mt], b_h[nt]);
                }
        }
        __syncthreads();
    }

#pragma unroll
    for (int mt = 0; mt < 2; mt++) {
        int r0 = wm * 32 + mt * 16 + (lane >> 2);
#pragma unroll
        for (int nt = 0; nt < 8; nt++) {
            int c0 = wn * 64 + nt * 8 + (lane & 3) * 2;
            float b0 = bias[c0], b1 = bias[c0 + 1];
            float2 v0 = make_float2(d[mt][nt][0] + b0, d[mt][nt][1] + b1);
            float2 v1 = make_float2(d[mt][nt][2] + b0, d[mt][nt][3] + b1);
            *(float2*)&C[(size_t)r0 * ldc + c0]       = v0;
            *(float2*)&C[(size_t)(r0 + 8) * ldc + c0] = v1;
        }
    }
}

__global__ __launch_bounds__(256, 1) void qkv_gemm_kernel(
    const float* __restrict__ bq,  const float* __restrict__ bk,
    const float* __restrict__ bv,  const float* __restrict__ baq,
    const float* __restrict__ bak, const float* __restrict__ bav)
{
    const int n0 = blockIdx.x * BN;
    const int m0 = blockIdx.y * BM;
    const int z  = blockIdx.z;
    const bool txt = (m0 < S_TXT);
    const int widx = txt ? (3 + z) : z;
    const float* bias = (z == 0) ? (txt ? baq : bq)
                      : (z == 1) ? (txt ? bak : bk)
                                 : (txt ? bav : bv);
    float* C = ((z == 0) ? g_Q : (z == 1) ? g_K : g_V)
               + (size_t)m0 * DMODEL + n0;
    const size_t wb = (size_t)widx * DMODEL * DMODEL + (size_t)n0 * DMODEL;
    gemm_tile_mma(g_Xhi + (size_t)m0 * DMODEL, g_Xlo + (size_t)m0 * DMODEL,
                  g_Whi + wb, g_Wlo + wb, bias + n0, C, DMODEL);
}

__global__ __launch_bounds__(256, 1) void outproj_gemm_kernel(
    const float* __restrict__ b_out, const float* __restrict__ b_add_out,
    float* __restrict__ out)
{
    const int n0 = blockIdx.x * BN;
    const int m0 = blockIdx.y * BM;
    const bool txt = (m0 < S_TXT);
    const int widx = txt ? 7 : 6;
    const float* bias = txt ? b_add_out : b_out;
    float* C = txt ? (out + ((size_t)S_IMG + m0) * DMODEL + n0)
                   : (out + (size_t)(m0 - S_TXT) * DMODEL + n0);
    const size_t wb = (size_t)widx * DMODEL * DMODEL + (size_t)n0 * DMODEL;
    gemm_tile_mma(g_Ohi + (size_t)m0 * DMODEL, g_Olo + (size_t)m0 * DMODEL,
                  g_Whi + wb, g_Wlo + wb, bias + n0, C, DMODEL);
}

// ---------------------------------------------------------------------------
// per-head RMSNorm + RoPE on Q and K -> split bf16 planes (scale folded into Q)
// ---------------------------------------------------------------------------
__global__ __launch_bounds__(128) void rmsrope_kernel(
    const float* __restrict__ nq,  const float* __restrict__ nk,
    const float* __restrict__ naq, const float* __restrict__ nak,
    const float* __restrict__ img_cos, const float* __restrict__ img_sin,
    const float* __restrict__ txt_cos, const float* __restrict__ txt_sin)
{
    const int sh = blockIdx.x;
    const int s  = sh / NH;
    const int h  = sh - s * NH;
    const int which = blockIdx.y;  // 0 = Q, 1 = K

    const float* buf = which ? g_K : g_Q;
    const float *nw, *ctab, *stab;
    int srow;
    if (s < S_TXT) {
        nw = which ? nak : naq; ctab = txt_cos; stab = txt_sin; srow = s;
    } else {
        nw = which ? nk : nq;   ctab = img_cos; stab = img_sin; srow = s - S_TXT;
    }

    const int d = threadIdx.x;
    const size_t pos = (size_t)s * DMODEL + h * HD + d;
    float v = buf[pos - d + d];  // buf[pos]
    v = buf[pos];

    float ss = v * v;
#pragma unroll
    for (int o = 16; o > 0; o >>= 1) ss += __shfl_xor_sync(0xffffffffu, ss, o);
    __shared__ float wsum[4];
    if ((d & 31) == 0) wsum[d >> 5] = ss;
    __syncthreads();
    ss = wsum[0] + wsum[1] + wsum[2] + wsum[3];

    float inv = rsqrtf(ss * (1.0f / HD) + 1e-6f);
    v = v * inv * nw[d];

    float partner = __shfl_xor_sync(0xffffffffu, v, 1);
    float c  = ctab[(size_t)srow * (HD / 2) + (d >> 1)];
    float sn = stab[(size_t)srow * (HD / 2) + (d >> 1)];
    float outv = (d & 1) ? fmaf(partner, sn, v * c) : (v * c - partner * sn);
    if (which == 0) outv *= 0.08838834764831845f;  // 1/sqrt(128) folded into Q

    __nv_bfloat16 hi = __float2bfloat16(outv);
    __nv_bfloat16 lo = __float2bfloat16(outv - __bfloat162float(hi));
    if (which == 0) { g_Qh[pos] = hi; g_Ql[pos] = lo; }
    else            { g_Kh[pos] = hi; g_Kl[pos] = lo; }
}

// ---------------------------------------------------------------------------
// flash attention on tensor cores (split-bf16 3-pass for QK^T and PV)
// grid: (S_ALL/128, NH), 256 threads (8 warps, 16 q-rows each)
// ---------------------------------------------------------------------------
#define FQT 128
#define FKT 64
#define FLDS 136                    // halves per smem row (128 + 8 pad)
#define FPLANE_Q (FQT * FLDS)       // halves
#define FPLANE_K (FKT * FLDS)
#define FQB (FPLANE_Q * 2)          // bytes: 34816
#define FKB (FPLANE_K * 2)          // bytes: 17408
#define FLASH_SMEM (2 * FQB + 8 * FKB)   // 208896

__device__ __forceinline__ void flash_load_kv(uint32_t dstbase, int k0,
                                              int hoff, int tid)
{
#pragma unroll
    for (int t = 0; t < 16; t++) {
        int i = tid + t * 256;          // 0..4095
        int plane = i >> 10;            // 0 Kh, 1 Kl, 2 Vh, 3 Vl
        int idx = i & 1023;
        int r = idx >> 4;
        int c = (idx & 15) * 8;
        const __nv_bfloat16* g = (plane == 0) ? g_Kh : (plane == 1) ? g_Kl
                               : (plane == 2) ? g_Vh : g_Vl;
        cp_async16(dstbase + (uint32_t)plane * FKB + (uint32_t)(r * FLDS + c) * 2,
                   g + (size_t)(k0 + r) * DMODEL + hoff + c);
    }
}

__global__ __launch_bounds__(256, 1) void flash_mma_kernel()
{
    const uint32_t base = smem_u32(dyn_sm);
    const int tid  = threadIdx.x;
    const int wid  = tid >> 5;
    const int lane = tid & 31;
    const int h    = blockIdx.y;
    const int hoff = h * HD;
    const int q0   = blockIdx.x * FQT;

    const uint32_t sQh = base;
    const uint32_t sKV = base + 2 * FQB;

    // load Q planes
#pragma unroll
    for (int t = 0; t < 16; t++) {
        int i = tid + t * 256;          // 0..4095
        int plane = i >> 11;
        int idx = i & 2047;
        int r = idx >> 4;
        int c = (idx & 15) * 8;
        const __nv_bfloat16* g = plane ? g_Ql : g_Qh;
        cp_async16(sQh + (uint32_t)plane * FQB + (uint32_t)(r * FLDS + c) * 2,
                   g + (size_t)(q0 + r) * DMODEL + hoff + c);
    }
    flash_load_kv(sKV, 0, hoff, tid);
    cp_commit();

    float o[16][4];
#pragma unroll
    for (int j = 0; j < 16; j++)
#pragma unroll
        for (int i = 0; i < 4; i++) o[j][i] = 0.0f;
    float m0 = -1e30f, m1 = -1e30f, l0 = 0.0f, l1 = 0.0f;

    const int wq0 = wid * 16;
    const uint32_t lrow  = lane & 15;
    const uint32_t lcolb = (lane >> 4) * 16;   // byte offset (8 halves)

    const int NKT = S_ALL / FKT;   // 44
    for (int kt = 0; kt < NKT; kt++) {
        const uint32_t bufb = sKV + (uint32_t)(kt & 1) * (4 * FKB);
        if (kt + 1 < NKT) {
            flash_load_kv(sKV + (uint32_t)((kt + 1) & 1) * (4 * FKB),
                          (kt + 1) * FKT, hoff, tid);
            cp_commit();
            cp_wait<1>();
        } else {
            cp_wait<0>();
        }
        __syncthreads();

        // ---- S = Q K^T (3-pass split) ----
        float s[8][4];
#pragma unroll
        for (int j = 0; j < 8; j++)
#pragma unroll
            for (int i = 0; i < 4; i++) s[j][i] = 0.0f;

#pragma unroll
        for (int ks = 0; ks < 8; ks++) {
            uint32_t qa = sQh + (uint32_t)((wq0 + lrow) * FLDS + ks * 16) * 2 + lcolb;
            uint32_t ah[4], al[4];
            ldsm_x4(ah, qa);
            ldsm_x4(al, qa + FQB);
#pragma unroll
            for (int ng = 0; ng < 4; ng++) {
                uint32_t ka = bufb + (uint32_t)((ng * 16 + lrow) * FLDS + ks * 16) * 2 + lcolb;
                uint32_t rh[4], rl[4];
                ldsm_x4(rh, ka);
                ldsm_x4(rl, ka + FKB);
                uint32_t bh0[2] = {rh[0], rh[2]}, bh1[2] = {rh[1], rh[3]};
                uint32_t bl0[2] = {rl[0], rl[2]}, bl1[2] = {rl[1], rl[3]};
                mma16816(s[2 * ng],     ah, bh0);
                mma16816(s[2 * ng],     ah, bl0);
                mma16816(s[2 * ng],     al, bh0);
                mma16816(s[2 * ng + 1], ah, bh1);
                mma16816(s[2 * ng + 1], ah, bl1);
                mma16816(s[2 * ng + 1], al, bh1);
            }
        }

        // ---- online softmax on fragments ----
        float mx0 = -1e30f, mx1 = -1e30f;
#pragma unroll
        for (int j = 0; j < 8; j++) {
            mx0 = fmaxf(mx0, fmaxf(s[j][0], s[j][1]));
            mx1 = fmaxf(mx1, fmaxf(s[j][2], s[j][3]));
        }
        mx0 = fmaxf(mx0, __shfl_xor_sync(0xffffffffu, mx0, 1));
        mx0 = fmaxf(mx0, __shfl_xor_sync(0xffffffffu, mx0, 2));
        mx1 = fmaxf(mx1, __shfl_xor_sync(0xffffffffu, mx1, 1));
        mx1 = fmaxf(mx1, __shfl_xor_sync(0xffffffffu, mx1, 2));
        float mn0 = fmaxf(m0, mx0);
        float mn1 = fmaxf(m1, mx1);
        float al0 = __expf(m0 - mn0);
        float al1 = __expf(m1 - mn1);
        float rs0 = 0.0f, rs1 = 0.0f;
#pragma unroll
        for (int j = 0; j < 8; j++) {
            s[j][0] = __expf(s[j][0] - mn0);
            s[j][1] = __expf(s[j][1] - mn0);
            s[j][2] = __expf(s[j][2] - mn1);
            s[j][3] = __expf(s[j][3] - mn1);
            rs0 += s[j][0] + s[j][1];
            rs1 += s[j][2] + s[j][3];
        }
        rs0 += __shfl_xor_sync(0xffffffffu, rs0, 1);
        rs0 += __shfl_xor_sync(0xffffffffu, rs0, 2);
        rs1 += __shfl_xor_sync(0xffffffffu, rs1, 1);
        rs1 += __shfl_xor_sync(0xffffffffu, rs1, 2);
        l0 = l0 * al0 + rs0;
        l1 = l1 * al1 + rs1;
        m0 = mn0;
        m1 = mn1;
#pragma unroll
        for (int j = 0; j < 16; j++) {
            o[j][0] *= al0; o[j][1] *= al0;
            o[j][2] *= al1; o[j][3] *= al1;
        }

        // ---- O += P V (3-pass split) ----
        const uint32_t Vb = bufb + 2 * FKB;
#pragma unroll
        for (int t = 0; t < 4; t++) {
            uint32_t aph[4], apl[4];
            split_pack2(s[2 * t][0],     s[2 * t][1],     aph[0], apl[0]);
            split_pack2(s[2 * t][2],     s[2 * t][3],     aph[1], apl[1]);
            split_pack2(s[2 * t + 1][0], s[2 * t + 1][1], aph[2], apl[2]);
            split_pack2(s[2 * t + 1][2], s[2 * t + 1][3], aph[3], apl[3]);
#pragma unroll
            for (int g = 0; g < 8; g++) {
                uint32_t va = Vb + (uint32_t)((t * 16 + lrow) * FLDS + g * 16) * 2 + lcolb;
                uint32_t rvh[4], rvl[4];
                ldsm_x4_t(rvh, va);
                ldsm_x4_t(rvl, va + FKB);
                uint32_t bh0[2] = {rvh[0], rvh[1]}, bh1[2] = {rvh[2], rvh[3]};
                uint32_t bl0[2] = {rvl[0], rvl[1]}, bl1[2] = {rvl[2], rvl[3]};
                mma16816(o[2 * g],     aph, bh0);
                mma16816(o[2 * g],     aph, bl0);
                mma16816(o[2 * g],     apl, bh0);
                mma16816(o[2 * g + 1], aph, bh1);
                mma16816(o[2 * g + 1], aph, bl1);
                mma16816(o[2 * g + 1], apl, bh1);
            }
        }
        __syncthreads();
    }

    // ---- epilogue: normalize, split to bf16 hi/lo planes ----
    float il0 = 1.0f / l0, il1 = 1.0f / l1;
    const int r0 = q0 + wq0 + (lane >> 2);
    const int r1 = r0 + 8;
    const int cb = hoff + (lane & 3) * 2;
#pragma unroll
    for (int j = 0; j < 16; j++) {
        int c = cb + j * 8;
        uint32_t hi, lo;
        split_pack2(o[j][0] * il0, o[j][1] * il0, hi, lo);
        *(uint32_t*)&g_Ohi[(size_t)r0 * DMODEL + c] = hi;
        *(uint32_t*)&g_Olo[(size_t)r0 * DMODEL + c] = lo;
        split_pack2(o[j][2] * il1, o[j][3] * il1, hi, lo);
        *(uint32_t*)&g_Ohi[(size_t)r1 * DMODEL + c] = hi;
        *(uint32_t*)&g_Olo[(size_t)r1 * DMODEL + c] = lo;
    }
}

// ---------------------------------------------------------------------------
extern "C" void kernel_launch(void* const* d_in, const int* in_sizes, int n_in,
                              void* d_out, int out_size)
{
    const float* hid   = (const float*)d_in[0];
    const float* enc   = (const float*)d_in[1];
    const float* wq    = (const float*)d_in[2];
    const float* bq    = (const float*)d_in[3];
    const float* wk    = (const float*)d_in[4];
    const float* bk    = (const float*)d_in[5];
    const float* wv    = (const float*)d_in[6];
    const float* bv    = (const float*)d_in[7];
    const float* waq   = (const float*)d_in[8];
    const float* baq   = (const float*)d_in[9];
    const float* wak   = (const float*)d_in[10];
    const float* bak   = (const float*)d_in[11];
    const float* wav   = (const float*)d_in[12];
    const float* bav   = (const float*)d_in[13];
    const float* nq    = (const float*)d_in[14];
    const float* nk    = (const float*)d_in[15];
    const float* naq   = (const float*)d_in[16];
    const float* nak   = (const float*)d_in[17];
    const float* w_out     = (const float*)d_in[18];
    const float* b_out     = (const float*)d_in[19];
    const float* w_add_out = (const float*)d_in[20];
    const float* b_add_out = (const float*)d_in[21];
    const float* img_cos = (const float*)d_in[22];
    const float* img_sin = (const float*)d_in[23];
    const float* txt_cos = (const float*)d_in[24];
    const float* txt_sin = (const float*)d_in[25];

    float* out = (float*)d_out;

    // prepass splits
    {
        size_t n4 = (size_t)S_ALL * DMODEL / 4;
        split_x_kernel<<<(unsigned)((n4 + 255) / 256), 256>>>(hid, enc);
        size_t w4 = (size_t)DMODEL * DMODEL / 4;
        dim3 gw((unsigned)((w4 + 255) / 256), 8);
        split_w_kernel<<<gw, 256>>>(wq, wk, wv, waq, wak, wav, w_out, w_add_out);
    }

    cudaFuncSetAttribute(qkv_gemm_kernel,
                         cudaFuncAttributeMaxDynamicSharedMemorySize,
                         GEMM_SMEM_BYTES);
    qkv_gemm_kernel<<<dim3(DMODEL / BN, S_ALL / BM, 3), 256, GEMM_SMEM_BYTES>>>(
        bq, bk, bv, baq, bak, bav);

    rmsrope_kernel<<<dim3(S_ALL * NH, 2), 128>>>(nq, nk, naq, nak,
                                                 img_cos, img_sin,
                                                 txt_cos, txt_sin);

    {
        size_t n4 = (size_t)S_ALL * DMODEL / 4;
        split_v_kernel<<<(unsigned)((n4 + 255) / 256), 256>>>();
    }

    cudaFuncSetAttribute(flash_mma_kernel,
                         cudaFuncAttributeMaxDynamicSharedMemorySize,
                         FLASH_SMEM);
    flash_mma_kernel<<<dim3(S_ALL / FQT, NH), 256, FLASH_SMEM>>>();

    cudaFuncSetAttribute(outproj_gemm_kernel,
                         cudaFuncAttributeMaxDynamicSharedMemorySize,
                         GEMM_SMEM_BYTES);
    outproj_gemm_kernel<<<dim3(DMODEL / BN, S_ALL / BM), 256, GEMM_SMEM_BYTES>>>(
        b_out, b_add_out, out);
}